// round 6
// baseline (speedup 1.0000x reference)
#include <cuda_runtime.h>
#include <cuda_bf16.h>
#include <cstdint>
#include <cstddef>

#define NN 100000
#define EDGES_MAX 800000

// ---------------- scratch (static __device__, no allocation) ----------------
__device__ __align__(256) float g_agg1[NN * 128];
__device__ __align__(256) float g_X1[(size_t)NN * 256];
__device__ __align__(256) float g_T2[NN * 128];
__device__ __align__(256) float g_X2[NN * 128];
__device__ __align__(256) float g_T3[NN * 40];
__device__ __align__(256) float g_outdeg[NN];
__device__ __align__(256) float g_indeg[NN];
__device__ __align__(256) float g_invout[NN];
__device__ __align__(256) float g_invin[NN];
// CSR (grouped by dst)
__device__ __align__(256) int g_rowinc[NN];
__device__ __align__(256) int g_rowstart[NN];
__device__ __align__(256) int g_ctr[NN];
__device__ __align__(256) int g_blocksum[128];
__device__ __align__(256) int g_csr[EDGES_MAX];
// W^T split-bf16 (hi/lo), layout [N][K] K-contiguous
__device__ __align__(256) __nv_bfloat16 g_Wt1h[256 * 128];
__device__ __align__(256) __nv_bfloat16 g_Wt1l[256 * 128];
__device__ __align__(256) __nv_bfloat16 g_Wt2h[128 * 256];
__device__ __align__(256) __nv_bfloat16 g_Wt2l[128 * 256];
__device__ __align__(256) __nv_bfloat16 g_Wt3h[40 * 128];
__device__ __align__(256) __nv_bfloat16 g_Wt3l[40 * 128];

// ---------------- prep ----------------
__device__ __forceinline__ void wsplit_one(const float* __restrict__ W, int K, int N, int i,
                                           __nv_bfloat16* __restrict__ th,
                                           __nv_bfloat16* __restrict__ tl) {
    int k = i / N, n = i % N;
    float w = W[i];
    __nv_bfloat16 h = __float2bfloat16(w);
    float r = w - __bfloat162float(h);
    th[n * K + k] = h;
    tl[n * K + k] = __float2bfloat16(r);
}

// NOTE: launched with >= NN threads
__global__ void prep_kernel(const float* __restrict__ W1, const float* __restrict__ W2,
                            const float* __restrict__ W3,
                            __nv_bfloat16* __restrict__ w1h, __nv_bfloat16* __restrict__ w1l,
                            __nv_bfloat16* __restrict__ w2h, __nv_bfloat16* __restrict__ w2l,
                            __nv_bfloat16* __restrict__ w3h, __nv_bfloat16* __restrict__ w3l,
                            float* __restrict__ outdeg, float* __restrict__ indeg) {
    int i = blockIdx.x * blockDim.x + threadIdx.x;
    if (i < NN) { outdeg[i] = 0.0f; indeg[i] = 0.0f; }
    if (i < 128 * 256) {
        wsplit_one(W1, 128, 256, i, w1h, w1l);
        wsplit_one(W2, 256, 128, i, w2h, w2l);
    }
    if (i < 128 * 40) wsplit_one(W3, 128, 40, i, w3h, w3l);
}

__global__ void degree_kernel(const int* __restrict__ src, const int* __restrict__ dst,
                              float* __restrict__ outdeg, float* __restrict__ indeg, int E) {
    int i = blockIdx.x * blockDim.x + threadIdx.x;
    if (i >= E) return;
    atomicAdd(&outdeg[src[i]], 1.0f);
    atomicAdd(&indeg[dst[i]], 1.0f);
}

// ---------------- 3-phase deterministic exclusive scan ----------------
__global__ __launch_bounds__(1024)
void scan1_kernel(const float* __restrict__ indeg, int* __restrict__ rowinc,
                  int* __restrict__ blocksum, int n) {
    __shared__ int sm[1024];
    int t = threadIdx.x;
    int i = blockIdx.x * 1024 + t;
    int v = (i < n) ? (int)indeg[i] : 0;
    sm[t] = v;
    __syncthreads();
    #pragma unroll
    for (int off = 1; off < 1024; off <<= 1) {
        int a = (t >= off) ? sm[t - off] : 0;
        __syncthreads();
        sm[t] += a;
        __syncthreads();
    }
    if (i < n) rowinc[i] = sm[t];
    if (t == 1023) blocksum[blockIdx.x] = sm[1023];
}

__global__ __launch_bounds__(128)
void scan2_kernel(int* __restrict__ blocksum, int nb) {
    __shared__ int sm[128];
    int t = threadIdx.x;
    int v = (t < nb) ? blocksum[t] : 0;
    sm[t] = v;
    __syncthreads();
    #pragma unroll
    for (int off = 1; off < 128; off <<= 1) {
        int a = (t >= off) ? sm[t - off] : 0;
        __syncthreads();
        sm[t] += a;
        __syncthreads();
    }
    if (t < nb) blocksum[t] = sm[t] - v;
}

__global__ void scan3_kernel(const int* __restrict__ rowinc, const float* __restrict__ indeg,
                             const float* __restrict__ outdeg, const int* __restrict__ blocksum,
                             int* __restrict__ rowstart, int* __restrict__ ctr,
                             float* __restrict__ invout, float* __restrict__ invin, int n) {
    int i = blockIdx.x * blockDim.x + threadIdx.x;
    if (i >= n) return;
    int rs = rowinc[i] - (int)indeg[i] + blocksum[i >> 10];
    rowstart[i] = rs;
    ctr[i] = rs;
    invout[i] = rsqrtf(fmaxf(outdeg[i], 1.0f));
    invin[i]  = rsqrtf(fmaxf(indeg[i], 1.0f));
}

__global__ void fill_kernel(const int* __restrict__ src, const int* __restrict__ dst,
                            int* __restrict__ ctr, int* __restrict__ csr, int E) {
    int i = blockIdx.x * blockDim.x + threadIdx.x;
    if (i >= E) return;
    int p = atomicAdd(&ctr[dst[i]], 1);
    csr[p] = src[i];
}

// ---------------- CSR gather aggregation: one warp per dst node ----------------
template <int F4, bool PRE, bool POST, bool RELU>
__global__ __launch_bounds__(256)
void agg_kernel(const float* __restrict__ H, const int* __restrict__ csr,
                const int* __restrict__ rowstart, const float* __restrict__ indeg,
                const float* __restrict__ pre, const float* __restrict__ invin,
                const float* __restrict__ bias, float* __restrict__ out, int n) {
    int w = (blockIdx.x * blockDim.x + threadIdx.x) >> 5;
    if (w >= n) return;
    int lane = threadIdx.x & 31;
    int start = rowstart[w];
    int deg = (int)indeg[w];

    float4 acc = make_float4(0.f, 0.f, 0.f, 0.f);
    const float4* Hv = reinterpret_cast<const float4*>(H);

    for (int base = 0; base < deg; base += 32) {
        int nchunk = min(32, deg - base);
        int idx = 0;
        float pval = 1.0f;
        if (lane < nchunk) {
            idx = csr[start + base + lane];
            if (PRE) pval = pre[idx];
        }
        #pragma unroll 4
        for (int j = 0; j < nchunk; ++j) {
            int s = __shfl_sync(0xffffffffu, idx, j);
            float p = PRE ? __shfl_sync(0xffffffffu, pval, j) : 1.0f;
            if (lane < F4) {
                float4 v = Hv[(size_t)s * F4 + lane];
                if (PRE) {
                    acc.x = fmaf(v.x, p, acc.x);
                    acc.y = fmaf(v.y, p, acc.y);
                    acc.z = fmaf(v.z, p, acc.z);
                    acc.w = fmaf(v.w, p, acc.w);
                } else {
                    acc.x += v.x; acc.y += v.y; acc.z += v.z; acc.w += v.w;
                }
            }
        }
    }

    if (lane < F4) {
        if (POST) {
            float s = invin[w];
            float4 b = reinterpret_cast<const float4*>(bias)[lane];
            acc.x = acc.x * s + b.x;
            acc.y = acc.y * s + b.y;
            acc.z = acc.z * s + b.z;
            acc.w = acc.w * s + b.w;
        }
        if (RELU) {
            acc.x = fmaxf(acc.x, 0.f); acc.y = fmaxf(acc.y, 0.f);
            acc.z = fmaxf(acc.z, 0.f); acc.w = fmaxf(acc.w, 0.f);
        }
        reinterpret_cast<float4*>(out)[(size_t)w * F4 + lane] = acc;
    }
}

// ---------------- mma.sync split-bf16 GEMM, double-buffered cp.async ----------------
__device__ __forceinline__ void mma16816(float* d, const uint32_t* a, uint32_t b0, uint32_t b1) {
    asm("mma.sync.aligned.m16n8k16.row.col.f32.bf16.bf16.f32 "
        "{%0,%1,%2,%3}, {%4,%5,%6,%7}, {%8,%9}, {%0,%1,%2,%3};"
        : "+f"(d[0]), "+f"(d[1]), "+f"(d[2]), "+f"(d[3])
        : "r"(a[0]), "r"(a[1]), "r"(a[2]), "r"(a[3]), "r"(b0), "r"(b1));
}

__device__ __forceinline__ uint32_t lds_u32e(const __nv_bfloat16* base, int eoff) {
    return *reinterpret_cast<const uint32_t*>(base + eoff);
}

__device__ __forceinline__ uint32_t smem_u32(const void* p) {
    uint32_t a;
    asm("{ .reg .u64 t; cvta.to.shared.u64 t, %1; cvt.u32.u64 %0, t; }" : "=r"(a) : "l"(p));
    return a;
}

constexpr int GLDW = 40;              // bf16 elems per smem row (32 + pad)
constexpr int GTILE_E = 128 * GLDW;   // elems per tile buffer (5120)
constexpr int GTILE_B = GTILE_E * 2;  // bytes (10240)
constexpr int GSMEM_BYTES = 8 * GTILE_B;  // 81920

template <bool PRE, bool POST, bool RELU>
__global__ __launch_bounds__(256)
void mgemm_kernel(const float* __restrict__ A,
                  const __nv_bfloat16* __restrict__ Wth,
                  const __nv_bfloat16* __restrict__ Wtl,
                  float* __restrict__ C, int M, int N, int K,
                  const float* __restrict__ pre,
                  const float* __restrict__ post,
                  const float* __restrict__ bias) {
    extern __shared__ __align__(16) char smem[];
    // layout: Ah0 Ah1 Al0 Al1 Wh0 Wh1 Wl0 Wl1
    __nv_bfloat16* sAh = reinterpret_cast<__nv_bfloat16*>(smem);
    __nv_bfloat16* sAl = sAh + 2 * GTILE_E;
    __nv_bfloat16* sWh = sAl + 2 * GTILE_E;
    __nv_bfloat16* sWl = sWh + 2 * GTILE_E;
    const uint32_t sWh_u = smem_u32(sWh);
    const uint32_t sWl_u = smem_u32(sWl);

    const int tid = threadIdx.x;
    const int lane = tid & 31;
    const int wid = tid >> 5;
    const int m0 = blockIdx.x * 128;
    const int n0 = blockIdx.y * 128;
    const int wm = (wid & 3) * 32;
    const int wn = (wid >> 2) * 64;
    const int g = lane >> 2;
    const int tg2 = (lane & 3) * 2;

    const int KC = K >> 5;   // 32-wide chunks
    float4 areg[4];
    float acc[2][8][4] = {};

    // ---- helpers (lambdas) ----
    auto load_A_regs = [&](int kc) {
        #pragma unroll
        for (int it = 0; it < 4; ++it) {
            int idx = it * 256 + tid;
            int row = idx >> 3;
            int c4 = idx & 7;
            int gr = m0 + row;
            float4 a = make_float4(0.f, 0.f, 0.f, 0.f);
            if (gr < M) {
                a = *reinterpret_cast<const float4*>(A + (size_t)gr * K + kc * 32 + c4 * 4);
                if (PRE) {
                    float s = pre[gr];
                    a.x *= s; a.y *= s; a.z *= s; a.w *= s;
                }
            }
            areg[it] = a;
        }
    };
    auto cp_async_W = [&](int kc, int b) {
        #pragma unroll
        for (int it = 0; it < 4; ++it) {
            int idx = it * 256 + tid;         // 0..1023
            bool lo = idx >= 512;
            int idx2 = idx & 511;
            int n = idx2 >> 2;                // 0..127
            int seg = idx2 & 3;               // 16B segment
            int gn = n0 + n;
            int cn = min(gn, N - 1);
            const __nv_bfloat16* gsrc = (lo ? Wtl : Wth) + (size_t)cn * K + kc * 32 + seg * 8;
            uint32_t dst = (lo ? sWl_u : sWh_u) + (uint32_t)(b * GTILE_B + n * (GLDW * 2) + seg * 16);
            int sz = (gn < N) ? 16 : 0;
            asm volatile("cp.async.ca.shared.global [%0], [%1], 16, %2;"
                         :: "r"(dst), "l"(gsrc), "r"(sz));
        }
        asm volatile("cp.async.commit_group;");
    };
    auto convert_sts_A = [&](int b) {
        #pragma unroll
        for (int it = 0; it < 4; ++it) {
            int idx = it * 256 + tid;
            int row = idx >> 3;
            int c4 = idx & 7;
            float4 a = areg[it];
            __nv_bfloat162 h01 = __floats2bfloat162_rn(a.x, a.y);
            __nv_bfloat162 h23 = __floats2bfloat162_rn(a.z, a.w);
            float l0 = a.x - __bfloat162float(h01.x);
            float l1 = a.y - __bfloat162float(h01.y);
            float l2 = a.z - __bfloat162float(h23.x);
            float l3 = a.w - __bfloat162float(h23.y);
            __nv_bfloat162 lo01 = __floats2bfloat162_rn(l0, l1);
            __nv_bfloat162 lo23 = __floats2bfloat162_rn(l2, l3);
            int eoff = b * GTILE_E + row * GLDW + c4 * 4;
            *reinterpret_cast<uint2*>(sAh + eoff) =
                make_uint2(*reinterpret_cast<uint32_t*>(&h01), *reinterpret_cast<uint32_t*>(&h23));
            *reinterpret_cast<uint2*>(sAl + eoff) =
                make_uint2(*reinterpret_cast<uint32_t*>(&lo01), *reinterpret_cast<uint32_t*>(&lo23));
        }
    };
    auto compute = [&](int b) {
        const __nv_bfloat16* Ah_ = sAh + b * GTILE_E;
        const __nv_bfloat16* Al_ = sAl + b * GTILE_E;
        const __nv_bfloat16* Wh_ = sWh + b * GTILE_E;
        const __nv_bfloat16* Wl_ = sWl + b * GTILE_E;
        #pragma unroll
        for (int ks = 0; ks < 2; ++ks) {
            int kk = ks * 16;
            uint32_t ah[2][4], al[2][4];
            #pragma unroll
            for (int mi = 0; mi < 2; ++mi) {
                int r = wm + mi * 16;
                ah[mi][0] = lds_u32e(Ah_, (r + g) * GLDW + kk + tg2);
                ah[mi][1] = lds_u32e(Ah_, (r + g + 8) * GLDW + kk + tg2);
                ah[mi][2] = lds_u32e(Ah_, (r + g) * GLDW + kk + tg2 + 8);
                ah[mi][3] = lds_u32e(Ah_, (r + g + 8) * GLDW + kk + tg2 + 8);
                al[mi][0] = lds_u32e(Al_, (r + g) * GLDW + kk + tg2);
                al[mi][1] = lds_u32e(Al_, (r + g + 8) * GLDW + kk + tg2);
                al[mi][2] = lds_u32e(Al_, (r + g) * GLDW + kk + tg2 + 8);
                al[mi][3] = lds_u32e(Al_, (r + g + 8) * GLDW + kk + tg2 + 8);
            }
            #pragma unroll
            for (int ni = 0; ni < 8; ++ni) {
                int n = wn + ni * 8 + g;
                uint32_t b0h = lds_u32e(Wh_, n * GLDW + kk + tg2);
                uint32_t b1h = lds_u32e(Wh_, n * GLDW + kk + tg2 + 8);
                uint32_t b0l = lds_u32e(Wl_, n * GLDW + kk + tg2);
                uint32_t b1l = lds_u32e(Wl_, n * GLDW + kk + tg2 + 8);
                mma16816(acc[0][ni], ah[0], b0h, b1h);
                mma16816(acc[1][ni], ah[1], b0h, b1h);
                mma16816(acc[0][ni], ah[0], b0l, b1l);
                mma16816(acc[1][ni], ah[1], b0l, b1l);
                mma16816(acc[0][ni], al[0], b0h, b1h);
                mma16816(acc[1][ni], al[1], b0h, b1h);
            }
        }
    };

    // ---- pipelined main loop ----
    load_A_regs(0);
    cp_async_W(0, 0);
    convert_sts_A(0);
    asm volatile("cp.async.wait_group 0;");
    __syncthreads();

    for (int kc = 0; kc < KC; ++kc) {
        int b = kc & 1;
        int nb = kc + 1;
        if (nb < KC) {
            load_A_regs(nb);
            cp_async_W(nb, nb & 1);
        }
        compute(b);
        if (nb < KC) {
            convert_sts_A(nb & 1);
            asm volatile("cp.async.wait_group 0;");
        }
        __syncthreads();
    }

    // ---- epilogue ----
    #pragma unroll
    for (int mi = 0; mi < 2; ++mi) {
        int r0 = m0 + wm + mi * 16 + g;
        int r1 = r0 + 8;
        float p0 = 1.f, p1 = 1.f;
        if (POST) {
            if (r0 < M) p0 = post[r0];
            if (r1 < M) p1 = post[r1];
        }
        #pragma unroll
        for (int ni = 0; ni < 8; ++ni) {
            int col = n0 + wn + ni * 8 + tg2;
            if (col >= N) continue;
            float bx = 0.f, by = 0.f;
            if (POST) { bx = bias[col]; by = bias[col + 1]; }
            if (r0 < M) {
                float vx = acc[mi][ni][0], vy = acc[mi][ni][1];
                if (POST) { vx = vx * p0 + bx; vy = vy * p0 + by; }
                if (RELU) { vx = fmaxf(vx, 0.f); vy = fmaxf(vy, 0.f); }
                *reinterpret_cast<float2*>(C + (size_t)r0 * N + col) = make_float2(vx, vy);
            }
            if (r1 < M) {
                float vx = acc[mi][ni][2], vy = acc[mi][ni][3];
                if (POST) { vx = vx * p1 + bx; vy = vy * p1 + by; }
                if (RELU) { vx = fmaxf(vx, 0.f); vy = fmaxf(vy, 0.f); }
                *reinterpret_cast<float2*>(C + (size_t)r1 * N + col) = make_float2(vx, vy);
            }
        }
    }
}

// ---------------- launch ----------------
static inline int cdiv(int a, int b) { return (a + b - 1) / b; }

extern "C" void kernel_launch(void* const* d_in, const int* in_sizes, int n_in,
                              void* d_out, int out_size) {
    const float* feat = (const float*)d_in[0];
    const int*   src  = (const int*)d_in[1];
    const int*   dst  = (const int*)d_in[2];
    const float* W1   = (const float*)d_in[3];
    const float* b1   = (const float*)d_in[4];
    const float* W2   = (const float*)d_in[5];
    const float* b2   = (const float*)d_in[6];
    const float* W3   = (const float*)d_in[7];
    const float* b3   = (const float*)d_in[8];
    const int E = in_sizes[1];
    float* out = (float*)d_out;

    float *agg1, *X1, *T2, *X2, *T3, *outdeg, *indeg, *invout, *invin;
    int *rowinc, *rowstart, *ctr, *blocksum, *csr;
    __nv_bfloat16 *wt1h, *wt1l, *wt2h, *wt2l, *wt3h, *wt3l;
    cudaGetSymbolAddress((void**)&agg1, g_agg1);
    cudaGetSymbolAddress((void**)&X1, g_X1);
    cudaGetSymbolAddress((void**)&T2, g_T2);
    cudaGetSymbolAddress((void**)&X2, g_X2);
    cudaGetSymbolAddress((void**)&T3, g_T3);
    cudaGetSymbolAddress((void**)&outdeg, g_outdeg);
    cudaGetSymbolAddress((void**)&indeg, g_indeg);
    cudaGetSymbolAddress((void**)&invout, g_invout);
    cudaGetSymbolAddress((void**)&invin, g_invin);
    cudaGetSymbolAddress((void**)&rowinc, g_rowinc);
    cudaGetSymbolAddress((void**)&rowstart, g_rowstart);
    cudaGetSymbolAddress((void**)&ctr, g_ctr);
    cudaGetSymbolAddress((void**)&blocksum, g_blocksum);
    cudaGetSymbolAddress((void**)&csr, g_csr);
    cudaGetSymbolAddress((void**)&wt1h, g_Wt1h);
    cudaGetSymbolAddress((void**)&wt1l, g_Wt1l);
    cudaGetSymbolAddress((void**)&wt2h, g_Wt2h);
    cudaGetSymbolAddress((void**)&wt2l, g_Wt2l);
    cudaGetSymbolAddress((void**)&wt3h, g_Wt3h);
    cudaGetSymbolAddress((void**)&wt3l, g_Wt3l);

    const int T = 256;
    const int MG = cdiv(NN, 128);
    const int AGG_GRID = cdiv(NN, 8);
    const int NB = cdiv(NN, 1024);

    cudaFuncSetAttribute(mgemm_kernel<false, true, true>,
                         cudaFuncAttributeMaxDynamicSharedMemorySize, GSMEM_BYTES);
    cudaFuncSetAttribute(mgemm_kernel<true, false, false>,
                         cudaFuncAttributeMaxDynamicSharedMemorySize, GSMEM_BYTES);

    // build pipeline
    prep_kernel<<<cdiv(NN, T), T>>>(W1, W2, W3, wt1h, wt1l, wt2h, wt2l,
                                    wt3h, wt3l, outdeg, indeg);
    degree_kernel<<<cdiv(E, T), T>>>(src, dst, outdeg, indeg, E);
    scan1_kernel<<<NB, 1024>>>(indeg, rowinc, blocksum, NN);
    scan2_kernel<<<1, 128>>>(blocksum, NB);
    scan3_kernel<<<cdiv(NN, T), T>>>(rowinc, indeg, outdeg, blocksum,
                                     rowstart, ctr, invout, invin, NN);
    fill_kernel<<<cdiv(E, T), T>>>(src, dst, ctr, csr, E);

    // ---- Layer 1: aggregate-first ----
    agg_kernel<32, true, false, false><<<AGG_GRID, T>>>(
        feat, csr, rowstart, indeg, invout, nullptr, nullptr, agg1, NN);
    {
        dim3 grid(MG, 2);
        mgemm_kernel<false, true, true><<<grid, T, GSMEM_BYTES>>>(
            agg1, wt1h, wt1l, X1, NN, 256, 128, nullptr, invin, b1);
    }

    // ---- Layer 2: transform-first ----
    {
        dim3 grid(MG, 1);
        mgemm_kernel<true, false, false><<<grid, T, GSMEM_BYTES>>>(
            X1, wt2h, wt2l, T2, NN, 128, 256, invout, nullptr, nullptr);
    }
    agg_kernel<32, false, true, true><<<AGG_GRID, T>>>(
        T2, csr, rowstart, indeg, nullptr, invin, b2, X2, NN);

    // ---- Layer 3: transform-first ----
    {
        dim3 grid(MG, 1);
        mgemm_kernel<true, false, false><<<grid, T, GSMEM_BYTES>>>(
            X2, wt3h, wt3l, T3, NN, 40, 128, invout, nullptr, nullptr);
    }
    agg_kernel<10, false, true, false><<<AGG_GRID, T>>>(
        T3, csr, rowstart, indeg, nullptr, invin, b3, out, NN);
}

// round 7
// speedup vs baseline: 1.0584x; 1.0584x over previous
#include <cuda_runtime.h>
#include <cuda_bf16.h>
#include <cstdint>
#include <cstddef>

#define NN 100000
#define EDGES_MAX 800000
#define NBLD 148
#define TBLD 1024
#define NPB ((NN + NBLD - 1) / NBLD)   // 676 nodes per build block

// ---------------- scratch (static __device__, no allocation) ----------------
__device__ __align__(256) float g_agg1[NN * 128];
__device__ __align__(256) float g_X1[(size_t)NN * 256];
__device__ __align__(256) float g_T2[NN * 128];
__device__ __align__(256) float g_X2[NN * 128];
__device__ __align__(256) float g_T3[NN * 40];
__device__ __align__(256) float g_invout[NN];
__device__ __align__(256) float g_invin[NN];
__device__ __align__(256) int g_odegi[NN];
__device__ __align__(256) int g_idegi[NN];
__device__ __align__(256) int g_rowstart[NN];
__device__ __align__(256) int g_ctr[NN];
__device__ __align__(256) int g_blocksum[NBLD];
__device__ __align__(256) int g_csr[EDGES_MAX];
__device__ unsigned g_barC;   // monotonic grid-barrier counter (never reset)
// W^T split-bf16 (hi/lo), layout [N][K] K-contiguous
__device__ __align__(256) __nv_bfloat16 g_Wt1h[256 * 128];
__device__ __align__(256) __nv_bfloat16 g_Wt1l[256 * 128];
__device__ __align__(256) __nv_bfloat16 g_Wt2h[128 * 256];
__device__ __align__(256) __nv_bfloat16 g_Wt2l[128 * 256];
__device__ __align__(256) __nv_bfloat16 g_Wt3h[40 * 128];
__device__ __align__(256) __nv_bfloat16 g_Wt3l[40 * 128];

// ---------------- fused build kernel (persistent, 148x1024) ----------------
__device__ __forceinline__ void grid_bar() {
    __syncthreads();
    __threadfence();
    if (threadIdx.x == 0) {
        unsigned old = atomicAdd(&g_barC, 1u);
        unsigned target = (old / NBLD + 1u) * NBLD;
        while (*(volatile unsigned*)&g_barC < target) { __nanosleep(64); }
    }
    __syncthreads();
}

__device__ __forceinline__ void wsplit_one(const float* __restrict__ W, int K, int N, int i,
                                           __nv_bfloat16* __restrict__ th,
                                           __nv_bfloat16* __restrict__ tl) {
    int k = i / N, n = i % N;
    float w = W[i];
    __nv_bfloat16 h = __float2bfloat16(w);
    float r = w - __bfloat162float(h);
    th[n * K + k] = h;
    tl[n * K + k] = __float2bfloat16(r);
}

__global__ __launch_bounds__(TBLD, 1)
void build_kernel(const int* __restrict__ src, const int* __restrict__ dst, int E,
                  const float* __restrict__ W1, const float* __restrict__ W2,
                  const float* __restrict__ W3) {
    __shared__ int sm_scan[TBLD];
    __shared__ int sm_bs[NBLD];

    const int t = threadIdx.x;
    const int b = blockIdx.x;
    const int gi = b * TBLD + t;

    // ---- phase a: zero degrees + split weights ----
    if (gi < NN) { g_odegi[gi] = 0; g_idegi[gi] = 0; }
    if (gi < 128 * 256) {
        wsplit_one(W1, 128, 256, gi, g_Wt1h, g_Wt1l);
        wsplit_one(W2, 256, 128, gi, g_Wt2h, g_Wt2l);
    }
    if (gi < 128 * 40) wsplit_one(W3, 128, 40, gi, g_Wt3h, g_Wt3l);
    grid_bar();

    // ---- phase b: degree histogram ----
    for (int e = gi; e < E; e += NBLD * TBLD) {
        atomicAdd(&g_odegi[src[e]], 1);
        atomicAdd(&g_idegi[dst[e]], 1);
    }
    grid_bar();

    // ---- phase c: local inclusive scan of in-degrees ----
    const int node = b * NPB + t;
    const int deg = (t < NPB && node < NN) ? g_idegi[node] : 0;
    sm_scan[t] = deg;
    __syncthreads();
    #pragma unroll
    for (int off = 1; off < TBLD; off <<= 1) {
        int a = (t >= off) ? sm_scan[t - off] : 0;
        __syncthreads();
        sm_scan[t] += a;
        __syncthreads();
    }
    const int incl = sm_scan[t];
    if (t == 0) g_blocksum[b] = sm_scan[TBLD - 1];
    grid_bar();

    // ---- phase d: cross-block prefix + rowstart/ctr/inv norms ----
    if (t < NBLD) sm_bs[t] = g_blocksum[t];
    __syncthreads();
    int off = 0;
    for (int j = 0; j < b; ++j) off += sm_bs[j];
    if (t < NPB && node < NN) {
        int rs = off + incl - deg;
        g_rowstart[node] = rs;
        g_ctr[node] = rs;
        g_invout[node] = rsqrtf(fmaxf((float)g_odegi[node], 1.0f));
        g_invin[node]  = rsqrtf(fmaxf((float)deg, 1.0f));
    }
    grid_bar();

    // ---- phase e: CSR fill ----
    for (int e = gi; e < E; e += NBLD * TBLD) {
        int p = atomicAdd(&g_ctr[dst[e]], 1);
        g_csr[p] = src[e];
    }
}

// ---------------- CSR gather aggregation: one warp per dst node ----------------
template <int F4, bool PRE, bool POST, bool RELU>
__global__ __launch_bounds__(256)
void agg_kernel(const float* __restrict__ H, const int* __restrict__ csr,
                const int* __restrict__ rowstart, const int* __restrict__ degi,
                const float* __restrict__ pre, const float* __restrict__ invin,
                const float* __restrict__ bias, float* __restrict__ out, int n) {
    int w = (blockIdx.x * blockDim.x + threadIdx.x) >> 5;
    if (w >= n) return;
    int lane = threadIdx.x & 31;
    int start = rowstart[w];
    int deg = degi[w];

    float4 acc = make_float4(0.f, 0.f, 0.f, 0.f);
    const float4* Hv = reinterpret_cast<const float4*>(H);

    for (int base = 0; base < deg; base += 32) {
        int nchunk = min(32, deg - base);
        int idx = 0;
        float pval = 1.0f;
        if (lane < nchunk) {
            idx = csr[start + base + lane];
            if (PRE) pval = pre[idx];
        }
        #pragma unroll 4
        for (int j = 0; j < nchunk; ++j) {
            int s = __shfl_sync(0xffffffffu, idx, j);
            float p = PRE ? __shfl_sync(0xffffffffu, pval, j) : 1.0f;
            if (lane < F4) {
                float4 v = Hv[(size_t)s * F4 + lane];
                if (PRE) {
                    acc.x = fmaf(v.x, p, acc.x);
                    acc.y = fmaf(v.y, p, acc.y);
                    acc.z = fmaf(v.z, p, acc.z);
                    acc.w = fmaf(v.w, p, acc.w);
                } else {
                    acc.x += v.x; acc.y += v.y; acc.z += v.z; acc.w += v.w;
                }
            }
        }
    }

    if (lane < F4) {
        if (POST) {
            float s = invin[w];
            float4 b = reinterpret_cast<const float4*>(bias)[lane];
            acc.x = acc.x * s + b.x;
            acc.y = acc.y * s + b.y;
            acc.z = acc.z * s + b.z;
            acc.w = acc.w * s + b.w;
        }
        if (RELU) {
            acc.x = fmaxf(acc.x, 0.f); acc.y = fmaxf(acc.y, 0.f);
            acc.z = fmaxf(acc.z, 0.f); acc.w = fmaxf(acc.w, 0.f);
        }
        reinterpret_cast<float4*>(out)[(size_t)w * F4 + lane] = acc;
    }
}

// ---------------- mma.sync split-bf16 GEMM (R5 body, templated N-tile) ----------------
__device__ __forceinline__ void mma16816(float* d, const uint32_t* a, uint32_t b0, uint32_t b1) {
    asm("mma.sync.aligned.m16n8k16.row.col.f32.bf16.bf16.f32 "
        "{%0,%1,%2,%3}, {%4,%5,%6,%7}, {%8,%9}, {%0,%1,%2,%3};"
        : "+f"(d[0]), "+f"(d[1]), "+f"(d[2]), "+f"(d[3])
        : "r"(a[0]), "r"(a[1]), "r"(a[2]), "r"(a[3]), "r"(b0), "r"(b1));
}

__device__ __forceinline__ uint32_t lds_u32(const __nv_bfloat16* p) {
    return *reinterpret_cast<const uint32_t*>(p);
}

constexpr int MMA_BK = 32;
constexpr int MMA_LDS = MMA_BK + 8;

// TNT = CTA N-tile (128 or 64). Warp grid 4(M) x 2(N); warp tile 32 x TNT/2.
template <int TNT, bool PRE, bool POST, bool RELU>
__global__ __launch_bounds__(256, 2)
void mgemm_kernel(const float* __restrict__ A,
                  const __nv_bfloat16* __restrict__ Wth,
                  const __nv_bfloat16* __restrict__ Wtl,
                  float* __restrict__ C, int M, int N, int K,
                  const float* __restrict__ pre,
                  const float* __restrict__ post,
                  const float* __restrict__ bias) {
    constexpr int NI = TNT / 16;       // 8-col groups per warp
    __shared__ __align__(16) __nv_bfloat16 Ah[128][MMA_LDS];
    __shared__ __align__(16) __nv_bfloat16 Al[128][MMA_LDS];
    __shared__ __align__(16) __nv_bfloat16 Wh[TNT][MMA_LDS];
    __shared__ __align__(16) __nv_bfloat16 Wl[TNT][MMA_LDS];

    const int tid = threadIdx.x;
    const int lane = tid & 31;
    const int wid = tid >> 5;
    const int m0 = blockIdx.x * 128;
    const int n0 = blockIdx.y * TNT;
    const int wm = (wid & 3) * 32;
    const int wn = (wid >> 2) * (TNT / 2);
    const int g = lane >> 2;
    const int tg2 = (lane & 3) * 2;

    float acc[2][NI][4] = {};

    for (int k0 = 0; k0 < K; k0 += MMA_BK) {
        if (k0 > 0) __syncthreads();
        // --- A chunk: fp32 coalesced load, split hi/lo bf16 into smem ---
        #pragma unroll
        for (int it = 0; it < 4; ++it) {
            int idx = it * 256 + tid;
            int row = idx >> 3;
            int c4 = idx & 7;
            int gr = m0 + row;
            float4 a = make_float4(0.f, 0.f, 0.f, 0.f);
            if (gr < M) {
                a = *reinterpret_cast<const float4*>(A + (size_t)gr * K + k0 + c4 * 4);
                if (PRE) {
                    float s = pre[gr];
                    a.x *= s; a.y *= s; a.z *= s; a.w *= s;
                }
            }
            __nv_bfloat162 h01 = __floats2bfloat162_rn(a.x, a.y);
            __nv_bfloat162 h23 = __floats2bfloat162_rn(a.z, a.w);
            float l0 = a.x - __bfloat162float(h01.x);
            float l1 = a.y - __bfloat162float(h01.y);
            float l2 = a.z - __bfloat162float(h23.x);
            float l3 = a.w - __bfloat162float(h23.y);
            __nv_bfloat162 lo01 = __floats2bfloat162_rn(l0, l1);
            __nv_bfloat162 lo23 = __floats2bfloat162_rn(l2, l3);
            uint32_t* ph = reinterpret_cast<uint32_t*>(&Ah[row][c4 * 4]);
            uint32_t* pl = reinterpret_cast<uint32_t*>(&Al[row][c4 * 4]);
            ph[0] = *reinterpret_cast<uint32_t*>(&h01);
            ph[1] = *reinterpret_cast<uint32_t*>(&h23);
            pl[0] = *reinterpret_cast<uint32_t*>(&lo01);
            pl[1] = *reinterpret_cast<uint32_t*>(&lo23);
        }
        // --- W chunk: pre-split bf16 [N][K], copy into smem ---
        #pragma unroll
        for (int it = 0; it < TNT / 16; ++it) {
            int idx = it * 256 + tid;
            int n = idx >> 4;
            int ku = idx & 15;
            int gn = n0 + n;
            uint32_t vh = 0, vl = 0;
            if (gn < N) {
                vh = *reinterpret_cast<const uint32_t*>(Wth + (size_t)gn * K + k0 + ku * 2);
                vl = *reinterpret_cast<const uint32_t*>(Wtl + (size_t)gn * K + k0 + ku * 2);
            }
            reinterpret_cast<uint32_t*>(&Wh[n][0])[ku] = vh;
            reinterpret_cast<uint32_t*>(&Wl[n][0])[ku] = vl;
        }
        __syncthreads();

        // --- 3 passes: Ah*Wh, Ah*Wl, Al*Wh ---
        #pragma unroll
        for (int pass = 0; pass < 3; ++pass) {
            const __nv_bfloat16 (*Asm)[MMA_LDS] = (pass == 2) ? Al : Ah;
            const __nv_bfloat16 (*Wsm)[MMA_LDS] = (pass == 1) ? Wl : Wh;
            #pragma unroll
            for (int ks = 0; ks < MMA_BK / 16; ++ks) {
                int kk = ks * 16;
                uint32_t afr[2][4];
                #pragma unroll
                for (int mi = 0; mi < 2; ++mi) {
                    int r = wm + mi * 16;
                    afr[mi][0] = lds_u32(&Asm[r + g][kk + tg2]);
                    afr[mi][1] = lds_u32(&Asm[r + g + 8][kk + tg2]);
                    afr[mi][2] = lds_u32(&Asm[r + g][kk + tg2 + 8]);
                    afr[mi][3] = lds_u32(&Asm[r + g + 8][kk + tg2 + 8]);
                }
                #pragma unroll
                for (int ni = 0; ni < NI; ++ni) {
                    int n = wn + ni * 8 + g;
                    uint32_t b0 = lds_u32(&Wsm[n][kk + tg2]);
                    uint32_t b1 = lds_u32(&Wsm[n][kk + tg2 + 8]);
                    mma16816(acc[0][ni], afr[0], b0, b1);
                    mma16816(acc[1][ni], afr[1], b0, b1);
                }
            }
        }
    }

    #pragma unroll
    for (int mi = 0; mi < 2; ++mi) {
        int r0 = m0 + wm + mi * 16 + g;
        int r1 = r0 + 8;
        float p0 = 1.f, p1 = 1.f;
        if (POST) {
            if (r0 < M) p0 = post[r0];
            if (r1 < M) p1 = post[r1];
        }
        #pragma unroll
        for (int ni = 0; ni < NI; ++ni) {
            int col = n0 + wn + ni * 8 + tg2;
            if (col >= N) continue;
            float bx = 0.f, by = 0.f;
            if (POST) { bx = bias[col]; by = bias[col + 1]; }
            if (r0 < M) {
                float vx = acc[mi][ni][0], vy = acc[mi][ni][1];
                if (POST) { vx = vx * p0 + bx; vy = vy * p0 + by; }
                if (RELU) { vx = fmaxf(vx, 0.f); vy = fmaxf(vy, 0.f); }
                *reinterpret_cast<float2*>(C + (size_t)r0 * N + col) = make_float2(vx, vy);
            }
            if (r1 < M) {
                float vx = acc[mi][ni][2], vy = acc[mi][ni][3];
                if (POST) { vx = vx * p1 + bx; vy = vy * p1 + by; }
                if (RELU) { vx = fmaxf(vx, 0.f); vy = fmaxf(vy, 0.f); }
                *reinterpret_cast<float2*>(C + (size_t)r1 * N + col) = make_float2(vx, vy);
            }
        }
    }
}

// ---------------- launch ----------------
static inline int cdiv(int a, int b) { return (a + b - 1) / b; }

extern "C" void kernel_launch(void* const* d_in, const int* in_sizes, int n_in,
                              void* d_out, int out_size) {
    const float* feat = (const float*)d_in[0];
    const int*   src  = (const int*)d_in[1];
    const int*   dst  = (const int*)d_in[2];
    const float* W1   = (const float*)d_in[3];
    const float* b1   = (const float*)d_in[4];
    const float* W2   = (const float*)d_in[5];
    const float* b2   = (const float*)d_in[6];
    const float* W3   = (const float*)d_in[7];
    const float* b3   = (const float*)d_in[8];
    const int E = in_sizes[1];
    float* out = (float*)d_out;

    float *agg1, *X1, *T2, *X2, *T3, *invout, *invin;
    int *idegi, *rowstart, *csr;
    __nv_bfloat16 *wt1h, *wt1l, *wt2h, *wt2l, *wt3h, *wt3l;
    cudaGetSymbolAddress((void**)&agg1, g_agg1);
    cudaGetSymbolAddress((void**)&X1, g_X1);
    cudaGetSymbolAddress((void**)&T2, g_T2);
    cudaGetSymbolAddress((void**)&X2, g_X2);
    cudaGetSymbolAddress((void**)&T3, g_T3);
    cudaGetSymbolAddress((void**)&invout, g_invout);
    cudaGetSymbolAddress((void**)&invin, g_invin);
    cudaGetSymbolAddress((void**)&idegi, g_idegi);
    cudaGetSymbolAddress((void**)&rowstart, g_rowstart);
    cudaGetSymbolAddress((void**)&csr, g_csr);
    cudaGetSymbolAddress((void**)&wt1h, g_Wt1h);
    cudaGetSymbolAddress((void**)&wt1l, g_Wt1l);
    cudaGetSymbolAddress((void**)&wt2h, g_Wt2h);
    cudaGetSymbolAddress((void**)&wt2l, g_Wt2l);
    cudaGetSymbolAddress((void**)&wt3h, g_Wt3h);
    cudaGetSymbolAddress((void**)&wt3l, g_Wt3l);

    const int T = 256;
    const int MG = cdiv(NN, 128);
    const int AGG_GRID = cdiv(NN, 8);

    // 0: fused build (degrees + scan + CSR + weight split + inv norms)
    build_kernel<<<NBLD, TBLD>>>(src, dst, E, W1, W2, W3);

    // ---- Layer 1: aggregate-first ----
    agg_kernel<32, true, false, false><<<AGG_GRID, T>>>(
        feat, csr, rowstart, idegi, invout, nullptr, nullptr, agg1, NN);
    {
        dim3 grid(MG, 2);
        mgemm_kernel<128, false, true, true><<<grid, T>>>(
            agg1, wt1h, wt1l, X1, NN, 256, 128, nullptr, invin, b1);
    }

    // ---- Layer 2: transform-first ----
    {
        dim3 grid(MG, 1);
        mgemm_kernel<128, true, false, false><<<grid, T>>>(
            X1, wt2h, wt2l, T2, NN, 128, 256, invout, nullptr, nullptr);
    }
    agg_kernel<32, false, true, true><<<AGG_GRID, T>>>(
        T2, csr, rowstart, idegi, nullptr, invin, b2, X2, NN);

    // ---- Layer 3: transform-first (N=40, 64-wide tile) ----
    {
        dim3 grid(MG, 1);
        mgemm_kernel<64, true, false, false><<<grid, T>>>(
            X2, wt3h, wt3l, T3, NN, 40, 128, invout, nullptr, nullptr);
    }
    agg_kernel<10, false, true, false><<<AGG_GRID, T>>>(
        T3, csr, rowstart, idegi, nullptr, invin, b3, out, NN);
}

// round 8
// speedup vs baseline: 1.0763x; 1.0169x over previous
#include <cuda_runtime.h>
#include <cuda_bf16.h>
#include <cstdint>
#include <cstddef>

#define NN 100000
#define EDGES_MAX 800000
#define NBLD 148
#define TBLD 1024
#define NPB ((NN + NBLD - 1) / NBLD)   // 676 nodes per build block

// ---------------- scratch (static __device__, no allocation) ----------------
__device__ __align__(256) float g_agg1[NN * 128];
__device__ __align__(256) float g_X1[(size_t)NN * 256];
__device__ __align__(256) float g_T2[NN * 128];
__device__ __align__(256) float g_X2[NN * 128];
__device__ __align__(256) float g_T3[NN * 40];
__device__ __align__(256) float g_invout[NN];
__device__ __align__(256) float g_invin[NN];
__device__ __align__(256) int g_odegi[NN];
__device__ __align__(256) int g_idegi[NN];
__device__ __align__(256) int g_rowstart[NN];
__device__ __align__(256) int g_ctr[NN];
__device__ __align__(256) int g_blocksum[NBLD];
__device__ __align__(256) int g_csr[EDGES_MAX];
__device__ unsigned g_barC;   // monotonic grid-barrier counter (never reset)
// W^T split-bf16 (hi/lo), layout [N][K] K-contiguous
__device__ __align__(256) __nv_bfloat16 g_Wt1h[256 * 128];
__device__ __align__(256) __nv_bfloat16 g_Wt1l[256 * 128];
__device__ __align__(256) __nv_bfloat16 g_Wt2h[128 * 256];
__device__ __align__(256) __nv_bfloat16 g_Wt2l[128 * 256];
__device__ __align__(256) __nv_bfloat16 g_Wt3h[40 * 128];
__device__ __align__(256) __nv_bfloat16 g_Wt3l[40 * 128];

// ---------------- fused build kernel (persistent, 148x1024) ----------------
__device__ __forceinline__ void grid_bar() {
    __syncthreads();
    __threadfence();
    if (threadIdx.x == 0) {
        unsigned old = atomicAdd(&g_barC, 1u);
        unsigned target = (old / NBLD + 1u) * NBLD;
        while (*(volatile unsigned*)&g_barC < target) { __nanosleep(64); }
    }
    __syncthreads();
}

__device__ __forceinline__ void wsplit_one(const float* __restrict__ W, int K, int N, int i,
                                           __nv_bfloat16* __restrict__ th,
                                           __nv_bfloat16* __restrict__ tl) {
    int k = i / N, n = i % N;
    float w = W[i];
    __nv_bfloat16 h = __float2bfloat16(w);
    float r = w - __bfloat162float(h);
    th[n * K + k] = h;
    tl[n * K + k] = __float2bfloat16(r);
}

__global__ __launch_bounds__(TBLD, 1)
void build_kernel(const int* __restrict__ src, const int* __restrict__ dst, int E,
                  const float* __restrict__ W1, const float* __restrict__ W2,
                  const float* __restrict__ W3) {
    __shared__ int sm_scan[TBLD];
    __shared__ int sm_bs[NBLD];

    const int t = threadIdx.x;
    const int b = blockIdx.x;
    const int gi = b * TBLD + t;

    // ---- phase a: zero degrees + split weights ----
    if (gi < NN) { g_odegi[gi] = 0; g_idegi[gi] = 0; }
    if (gi < 128 * 256) {
        wsplit_one(W1, 128, 256, gi, g_Wt1h, g_Wt1l);
        wsplit_one(W2, 256, 128, gi, g_Wt2h, g_Wt2l);
    }
    if (gi < 128 * 40) wsplit_one(W3, 128, 40, gi, g_Wt3h, g_Wt3l);
    grid_bar();

    // ---- phase b: degree histogram ----
    for (int e = gi; e < E; e += NBLD * TBLD) {
        atomicAdd(&g_odegi[src[e]], 1);
        atomicAdd(&g_idegi[dst[e]], 1);
    }
    grid_bar();

    // ---- phase c: local inclusive scan of in-degrees ----
    const int node = b * NPB + t;
    const int deg = (t < NPB && node < NN) ? g_idegi[node] : 0;
    sm_scan[t] = deg;
    __syncthreads();
    #pragma unroll
    for (int off = 1; off < TBLD; off <<= 1) {
        int a = (t >= off) ? sm_scan[t - off] : 0;
        __syncthreads();
        sm_scan[t] += a;
        __syncthreads();
    }
    const int incl = sm_scan[t];
    if (t == 0) g_blocksum[b] = sm_scan[TBLD - 1];
    grid_bar();

    // ---- phase d: cross-block prefix + rowstart/ctr/inv norms ----
    if (t < NBLD) sm_bs[t] = g_blocksum[t];
    __syncthreads();
    int off = 0;
    for (int j = 0; j < b; ++j) off += sm_bs[j];
    if (t < NPB && node < NN) {
        int rs = off + incl - deg;
        g_rowstart[node] = rs;
        g_ctr[node] = rs;
        g_invout[node] = rsqrtf(fmaxf((float)g_odegi[node], 1.0f));
        g_invin[node]  = rsqrtf(fmaxf((float)deg, 1.0f));
    }
    grid_bar();

    // ---- phase e: CSR fill ----
    for (int e = gi; e < E; e += NBLD * TBLD) {
        int p = atomicAdd(&g_ctr[dst[e]], 1);
        g_csr[p] = src[e];
    }
}

// ---------------- CSR gather aggregation: one warp per dst node ----------------
template <int F4, bool PRE, bool POST, bool RELU>
__global__ __launch_bounds__(256)
void agg_kernel(const float* __restrict__ H, const int* __restrict__ csr,
                const int* __restrict__ rowstart, const int* __restrict__ degi,
                const float* __restrict__ pre, const float* __restrict__ invin,
                const float* __restrict__ bias, float* __restrict__ out, int n) {
    int w = (blockIdx.x * blockDim.x + threadIdx.x) >> 5;
    if (w >= n) return;
    int lane = threadIdx.x & 31;
    int start = rowstart[w];
    int deg = degi[w];

    float4 acc = make_float4(0.f, 0.f, 0.f, 0.f);
    const float4* Hv = reinterpret_cast<const float4*>(H);

    for (int base = 0; base < deg; base += 32) {
        int nchunk = min(32, deg - base);
        int idx = 0;
        float pval = 1.0f;
        if (lane < nchunk) {
            idx = csr[start + base + lane];
            if (PRE) pval = pre[idx];
        }
        #pragma unroll 4
        for (int j = 0; j < nchunk; ++j) {
            int s = __shfl_sync(0xffffffffu, idx, j);
            float p = PRE ? __shfl_sync(0xffffffffu, pval, j) : 1.0f;
            if (lane < F4) {
                float4 v = Hv[(size_t)s * F4 + lane];
                if (PRE) {
                    acc.x = fmaf(v.x, p, acc.x);
                    acc.y = fmaf(v.y, p, acc.y);
                    acc.z = fmaf(v.z, p, acc.z);
                    acc.w = fmaf(v.w, p, acc.w);
                } else {
                    acc.x += v.x; acc.y += v.y; acc.z += v.z; acc.w += v.w;
                }
            }
        }
    }

    if (lane < F4) {
        if (POST) {
            float s = invin[w];
            float4 b = reinterpret_cast<const float4*>(bias)[lane];
            acc.x = acc.x * s + b.x;
            acc.y = acc.y * s + b.y;
            acc.z = acc.z * s + b.z;
            acc.w = acc.w * s + b.w;
        }
        if (RELU) {
            acc.x = fmaxf(acc.x, 0.f); acc.y = fmaxf(acc.y, 0.f);
            acc.z = fmaxf(acc.z, 0.f); acc.w = fmaxf(acc.w, 0.f);
        }
        reinterpret_cast<float4*>(out)[(size_t)w * F4 + lane] = acc;
    }
}

// ---------------- mma.sync split-bf16 GEMM with ldmatrix ----------------
__device__ __forceinline__ void mma16816(float* d, const uint32_t* a, uint32_t b0, uint32_t b1) {
    asm("mma.sync.aligned.m16n8k16.row.col.f32.bf16.bf16.f32 "
        "{%0,%1,%2,%3}, {%4,%5,%6,%7}, {%8,%9}, {%0,%1,%2,%3};"
        : "+f"(d[0]), "+f"(d[1]), "+f"(d[2]), "+f"(d[3])
        : "r"(a[0]), "r"(a[1]), "r"(a[2]), "r"(a[3]), "r"(b0), "r"(b1));
}

__device__ __forceinline__ void ldmat_x4(uint32_t* r, uint32_t saddr) {
    asm volatile("ldmatrix.sync.aligned.m8n8.x4.shared.b16 {%0,%1,%2,%3}, [%4];"
                 : "=r"(r[0]), "=r"(r[1]), "=r"(r[2]), "=r"(r[3]) : "r"(saddr));
}

__device__ __forceinline__ uint32_t smem_u32(const void* p) {
    uint32_t a;
    asm("{ .reg .u64 t; cvta.to.shared.u64 t, %1; cvt.u32.u64 %0, t; }" : "=r"(a) : "l"(p));
    return a;
}

constexpr int MMA_BK = 32;
constexpr int MMA_LDS = MMA_BK + 8;   // 40 elems = 80B rows -> conflict-free ldmatrix

// TNT = CTA N-tile (128 or 64). Warp grid 4(M) x 2(N); warp tile 32 x TNT/2.
template <int TNT, bool PRE, bool POST, bool RELU>
__global__ __launch_bounds__(256, 2)
void mgemm_kernel(const float* __restrict__ A,
                  const __nv_bfloat16* __restrict__ Wth,
                  const __nv_bfloat16* __restrict__ Wtl,
                  float* __restrict__ C, int M, int N, int K,
                  const float* __restrict__ pre,
                  const float* __restrict__ post,
                  const float* __restrict__ bias) {
    constexpr int NI = TNT / 16;       // 8-col groups per warp (8 or 4)
    __shared__ __align__(16) __nv_bfloat16 Ah[128][MMA_LDS];
    __shared__ __align__(16) __nv_bfloat16 Al[128][MMA_LDS];
    __shared__ __align__(16) __nv_bfloat16 Wh[TNT][MMA_LDS];
    __shared__ __align__(16) __nv_bfloat16 Wl[TNT][MMA_LDS];

    const int tid = threadIdx.x;
    const int lane = tid & 31;
    const int wid = tid >> 5;
    const int m0 = blockIdx.x * 128;
    const int n0 = blockIdx.y * TNT;
    const int wm = (wid & 3) * 32;
    const int wn = (wid >> 2) * (TNT / 2);
    const int g = lane >> 2;
    const int tg2 = (lane & 3) * 2;

    // ldmatrix per-lane address components
    const int arow = lane & 15;                       // A: lanes 0-15 k-low, 16-31 k-high
    const int akoff = (lane >> 4) * 8;
    const int wrow = (lane & 7) + ((lane >> 4) << 3); // W: n row within 16-group
    const int wkoff = (lane & 8) ? 8 : 0;

    const uint32_t uAh = smem_u32(&Ah[0][0]);
    const uint32_t uAl = smem_u32(&Al[0][0]);
    const uint32_t uWh = smem_u32(&Wh[0][0]);
    const uint32_t uWl = smem_u32(&Wl[0][0]);

    float acc[2][NI][4] = {};

    for (int k0 = 0; k0 < K; k0 += MMA_BK) {
        if (k0 > 0) __syncthreads();
        // --- A chunk: fp32 coalesced load, split hi/lo bf16 into smem ---
        #pragma unroll
        for (int it = 0; it < 4; ++it) {
            int idx = it * 256 + tid;
            int row = idx >> 3;
            int c4 = idx & 7;
            int gr = m0 + row;
            float4 a = make_float4(0.f, 0.f, 0.f, 0.f);
            if (gr < M) {
                a = *reinterpret_cast<const float4*>(A + (size_t)gr * K + k0 + c4 * 4);
                if (PRE) {
                    float s = pre[gr];
                    a.x *= s; a.y *= s; a.z *= s; a.w *= s;
                }
            }
            __nv_bfloat162 h01 = __floats2bfloat162_rn(a.x, a.y);
            __nv_bfloat162 h23 = __floats2bfloat162_rn(a.z, a.w);
            float l0 = a.x - __bfloat162float(h01.x);
            float l1 = a.y - __bfloat162float(h01.y);
            float l2 = a.z - __bfloat162float(h23.x);
            float l3 = a.w - __bfloat162float(h23.y);
            __nv_bfloat162 lo01 = __floats2bfloat162_rn(l0, l1);
            __nv_bfloat162 lo23 = __floats2bfloat162_rn(l2, l3);
            uint32_t* ph = reinterpret_cast<uint32_t*>(&Ah[row][c4 * 4]);
            uint32_t* pl = reinterpret_cast<uint32_t*>(&Al[row][c4 * 4]);
            ph[0] = *reinterpret_cast<uint32_t*>(&h01);
            ph[1] = *reinterpret_cast<uint32_t*>(&h23);
            pl[0] = *reinterpret_cast<uint32_t*>(&lo01);
            pl[1] = *reinterpret_cast<uint32_t*>(&lo23);
        }
        // --- W chunk: pre-split bf16 [N][K], copy into smem ---
        #pragma unroll
        for (int it = 0; it < TNT / 16; ++it) {
            int idx = it * 256 + tid;
            int n = idx >> 4;
            int ku = idx & 15;
            int gn = n0 + n;
            uint32_t vh = 0, vl = 0;
            if (gn < N) {
                vh = *reinterpret_cast<const uint32_t*>(Wth + (size_t)gn * K + k0 + ku * 2);
                vl = *reinterpret_cast<const uint32_t*>(Wtl + (size_t)gn * K + k0 + ku * 2);
            }
            reinterpret_cast<uint32_t*>(&Wh[n][0])[ku] = vh;
            reinterpret_cast<uint32_t*>(&Wl[n][0])[ku] = vl;
        }
        __syncthreads();

        // --- compute: ldmatrix fragments once, 3 split passes fused ---
        #pragma unroll
        for (int ks = 0; ks < 2; ++ks) {
            int kk = ks * 16;
            uint32_t ah[2][4], al[2][4];
            #pragma unroll
            for (int mi = 0; mi < 2; ++mi) {
                uint32_t aoff = (uint32_t)(((wm + mi * 16 + arow) * MMA_LDS + kk + akoff) * 2);
                ldmat_x4(ah[mi], uAh + aoff);
                ldmat_x4(al[mi], uAl + aoff);
            }
            #pragma unroll
            for (int nj = 0; nj < NI / 2; ++nj) {
                uint32_t wh[4], wl[4];
                uint32_t woff = (uint32_t)(((wn + nj * 16 + wrow) * MMA_LDS + kk + wkoff) * 2);
                ldmat_x4(wh, uWh + woff);
                ldmat_x4(wl, uWl + woff);
                #pragma unroll
                for (int q = 0; q < 2; ++q) {
                    int ni = nj * 2 + q;
                    uint32_t b0h = wh[q * 2], b1h = wh[q * 2 + 1];
                    uint32_t b0l = wl[q * 2], b1l = wl[q * 2 + 1];
                    mma16816(acc[0][ni], ah[0], b0h, b1h);
                    mma16816(acc[1][ni], ah[1], b0h, b1h);
                    mma16816(acc[0][ni], ah[0], b0l, b1l);
                    mma16816(acc[1][ni], ah[1], b0l, b1l);
                    mma16816(acc[0][ni], al[0], b0h, b1h);
                    mma16816(acc[1][ni], al[1], b0h, b1h);
                }
            }
        }
    }

    // ---- epilogue ----
    #pragma unroll
    for (int mi = 0; mi < 2; ++mi) {
        int r0 = m0 + wm + mi * 16 + g;
        int r1 = r0 + 8;
        float p0 = 1.f, p1 = 1.f;
        if (POST) {
            if (r0 < M) p0 = post[r0];
            if (r1 < M) p1 = post[r1];
        }
        #pragma unroll
        for (int ni = 0; ni < NI; ++ni) {
            int col = n0 + wn + ni * 8 + tg2;
            if (col >= N) continue;
            float bx = 0.f, by = 0.f;
            if (POST) { bx = bias[col]; by = bias[col + 1]; }
            if (r0 < M) {
                float vx = acc[mi][ni][0], vy = acc[mi][ni][1];
                if (POST) { vx = vx * p0 + bx; vy = vy * p0 + by; }
                if (RELU) { vx = fmaxf(vx, 0.f); vy = fmaxf(vy, 0.f); }
                *reinterpret_cast<float2*>(C + (size_t)r0 * N + col) = make_float2(vx, vy);
            }
            if (r1 < M) {
                float vx = acc[mi][ni][2], vy = acc[mi][ni][3];
                if (POST) { vx = vx * p1 + bx; vy = vy * p1 + by; }
                if (RELU) { vx = fmaxf(vx, 0.f); vy = fmaxf(vy, 0.f); }
                *reinterpret_cast<float2*>(C + (size_t)r1 * N + col) = make_float2(vx, vy);
            }
        }
    }
}

// ---------------- launch ----------------
static inline int cdiv(int a, int b) { return (a + b - 1) / b; }

extern "C" void kernel_launch(void* const* d_in, const int* in_sizes, int n_in,
                              void* d_out, int out_size) {
    const float* feat = (const float*)d_in[0];
    const int*   src  = (const int*)d_in[1];
    const int*   dst  = (const int*)d_in[2];
    const float* W1   = (const float*)d_in[3];
    const float* b1   = (const float*)d_in[4];
    const float* W2   = (const float*)d_in[5];
    const float* b2   = (const float*)d_in[6];
    const float* W3   = (const float*)d_in[7];
    const float* b3   = (const float*)d_in[8];
    const int E = in_sizes[1];
    float* out = (float*)d_out;

    float *agg1, *X1, *T2, *X2, *T3, *invout, *invin;
    int *idegi, *rowstart, *csr;
    __nv_bfloat16 *wt1h, *wt1l, *wt2h, *wt2l, *wt3h, *wt3l;
    cudaGetSymbolAddress((void**)&agg1, g_agg1);
    cudaGetSymbolAddress((void**)&X1, g_X1);
    cudaGetSymbolAddress((void**)&T2, g_T2);
    cudaGetSymbolAddress((void**)&X2, g_X2);
    cudaGetSymbolAddress((void**)&T3, g_T3);
    cudaGetSymbolAddress((void**)&invout, g_invout);
    cudaGetSymbolAddress((void**)&invin, g_invin);
    cudaGetSymbolAddress((void**)&idegi, g_idegi);
    cudaGetSymbolAddress((void**)&rowstart, g_rowstart);
    cudaGetSymbolAddress((void**)&csr, g_csr);
    cudaGetSymbolAddress((void**)&wt1h, g_Wt1h);
    cudaGetSymbolAddress((void**)&wt1l, g_Wt1l);
    cudaGetSymbolAddress((void**)&wt2h, g_Wt2h);
    cudaGetSymbolAddress((void**)&wt2l, g_Wt2l);
    cudaGetSymbolAddress((void**)&wt3h, g_Wt3h);
    cudaGetSymbolAddress((void**)&wt3l, g_Wt3l);

    const int T = 256;
    const int MG = cdiv(NN, 128);
    const int AGG_GRID = cdiv(NN, 8);

    // fused build (degrees + scan + CSR + weight split + inv norms)
    build_kernel<<<NBLD, TBLD>>>(src, dst, E, W1, W2, W3);

    // ---- Layer 1: aggregate-first ----
    agg_kernel<32, true, false, false><<<AGG_GRID, T>>>(
        feat, csr, rowstart, idegi, invout, nullptr, nullptr, agg1, NN);
    {
        dim3 grid(MG, 2);
        mgemm_kernel<128, false, true, true><<<grid, T>>>(
            agg1, wt1h, wt1l, X1, NN, 256, 128, nullptr, invin, b1);
    }

    // ---- Layer 2: transform-first ----
    {
        dim3 grid(MG, 1);
        mgemm_kernel<128, true, false, false><<<grid, T>>>(
            X1, wt2h, wt2l, T2, NN, 128, 256, invout, nullptr, nullptr);
    }
    agg_kernel<32, false, true, true><<<AGG_GRID, T>>>(
        T2, csr, rowstart, idegi, nullptr, invin, b2, X2, NN);

    // ---- Layer 3: transform-first (N=40, 64-wide tile) ----
    {
        dim3 grid(MG, 1);
        mgemm_kernel<64, true, false, false><<<grid, T>>>(
            X2, wt3h, wt3l, T3, NN, 40, 128, invout, nullptr, nullptr);
    }
    agg_kernel<10, false, true, false><<<AGG_GRID, T>>>(
        T3, csr, rowstart, idegi, nullptr, invin, b3, out, NN);
}

// round 9
// speedup vs baseline: 1.0978x; 1.0200x over previous
#include <cuda_runtime.h>
#include <cuda_bf16.h>
#include <cstdint>
#include <cstddef>

#define NN 100000
#define EDGES_MAX 800000
#define NBLD 148
#define TBLD 1024
#define NPB ((NN + NBLD - 1) / NBLD)

// ---------------- scratch (static __device__, no allocation) ----------------
// split-bf16 activation buffers (hi/lo)
__device__ __align__(256) __nv_bfloat16 g_A1h[(size_t)NN * 128];
__device__ __align__(256) __nv_bfloat16 g_A1l[(size_t)NN * 128];
__device__ __align__(256) __nv_bfloat16 g_X1h[(size_t)NN * 256];
__device__ __align__(256) __nv_bfloat16 g_X1l[(size_t)NN * 256];
__device__ __align__(256) __nv_bfloat16 g_X2h[(size_t)NN * 128];
__device__ __align__(256) __nv_bfloat16 g_X2l[(size_t)NN * 128];
__device__ __align__(256) float g_T2[NN * 128];
__device__ __align__(256) float g_T3[NN * 40];
__device__ __align__(256) float g_invout[NN];
__device__ __align__(256) float g_invin[NN];
__device__ __align__(256) int g_odegi[NN];
__device__ __align__(256) int g_idegi[NN];
__device__ __align__(256) int g_rowstart[NN];
__device__ __align__(256) int g_ctr[NN];
__device__ __align__(256) int g_blocksum[NBLD];
__device__ __align__(256) int g_csr[EDGES_MAX];
__device__ unsigned g_barC;
// W^T split-bf16 (hi/lo), layout [N][K] K-contiguous
__device__ __align__(256) __nv_bfloat16 g_Wt1h[256 * 128];
__device__ __align__(256) __nv_bfloat16 g_Wt1l[256 * 128];
__device__ __align__(256) __nv_bfloat16 g_Wt2h[128 * 256];
__device__ __align__(256) __nv_bfloat16 g_Wt2l[128 * 256];
__device__ __align__(256) __nv_bfloat16 g_Wt3h[40 * 128];
__device__ __align__(256) __nv_bfloat16 g_Wt3l[40 * 128];

__device__ __forceinline__ uint32_t pack_bf2(float x, float y) {
    __nv_bfloat162 t = __floats2bfloat162_rn(x, y);
    return *reinterpret_cast<uint32_t*>(&t);
}
__device__ __forceinline__ void split2(float x, float y, uint32_t& hi, uint32_t& lo) {
    __nv_bfloat162 h = __floats2bfloat162_rn(x, y);
    float rx = x - __bfloat162float(h.x);
    float ry = y - __bfloat162float(h.y);
    hi = *reinterpret_cast<uint32_t*>(&h);
    lo = pack_bf2(rx, ry);
}

// ---------------- fused build kernel (persistent, 148x1024) ----------------
__device__ __forceinline__ void grid_bar() {
    __syncthreads();
    __threadfence();
    if (threadIdx.x == 0) {
        unsigned old = atomicAdd(&g_barC, 1u);
        unsigned target = (old / NBLD + 1u) * NBLD;
        while (*(volatile unsigned*)&g_barC < target) { __nanosleep(64); }
    }
    __syncthreads();
}

__device__ __forceinline__ void wsplit_one(const float* __restrict__ W, int K, int N, int i,
                                           __nv_bfloat16* __restrict__ th,
                                           __nv_bfloat16* __restrict__ tl) {
    int k = i / N, n = i % N;
    float w = W[i];
    __nv_bfloat16 h = __float2bfloat16(w);
    float r = w - __bfloat162float(h);
    th[n * K + k] = h;
    tl[n * K + k] = __float2bfloat16(r);
}

__global__ __launch_bounds__(TBLD, 1)
void build_kernel(const int* __restrict__ src, const int* __restrict__ dst, int E,
                  const float* __restrict__ W1, const float* __restrict__ W2,
                  const float* __restrict__ W3) {
    __shared__ int sm_scan[TBLD];
    __shared__ int sm_bs[NBLD];

    const int t = threadIdx.x;
    const int b = blockIdx.x;
    const int gi = b * TBLD + t;

    if (gi < NN) { g_odegi[gi] = 0; g_idegi[gi] = 0; }
    if (gi < 128 * 256) {
        wsplit_one(W1, 128, 256, gi, g_Wt1h, g_Wt1l);
        wsplit_one(W2, 256, 128, gi, g_Wt2h, g_Wt2l);
    }
    if (gi < 128 * 40) wsplit_one(W3, 128, 40, gi, g_Wt3h, g_Wt3l);
    grid_bar();

    for (int e = gi; e < E; e += NBLD * TBLD) {
        atomicAdd(&g_odegi[src[e]], 1);
        atomicAdd(&g_idegi[dst[e]], 1);
    }
    grid_bar();

    const int node = b * NPB + t;
    const int deg = (t < NPB && node < NN) ? g_idegi[node] : 0;
    sm_scan[t] = deg;
    __syncthreads();
    #pragma unroll
    for (int off = 1; off < TBLD; off <<= 1) {
        int a = (t >= off) ? sm_scan[t - off] : 0;
        __syncthreads();
        sm_scan[t] += a;
        __syncthreads();
    }
    const int incl = sm_scan[t];
    if (t == 0) g_blocksum[b] = sm_scan[TBLD - 1];
    grid_bar();

    if (t < NBLD) sm_bs[t] = g_blocksum[t];
    __syncthreads();
    int off = 0;
    for (int j = 0; j < b; ++j) off += sm_bs[j];
    if (t < NPB && node < NN) {
        int rs = off + incl - deg;
        g_rowstart[node] = rs;
        g_ctr[node] = rs;
        g_invout[node] = rsqrtf(fmaxf((float)g_odegi[node], 1.0f));
        g_invin[node]  = rsqrtf(fmaxf((float)deg, 1.0f));
    }
    grid_bar();

    for (int e = gi; e < E; e += NBLD * TBLD) {
        int p = atomicAdd(&g_ctr[dst[e]], 1);
        g_csr[p] = src[e];
    }
}

// ---------------- CSR gather aggregation ----------------
// MODE 0: out split-bf16 of raw sum (pre applied per-source)            (agg1)
// MODE 1: v = relu(sum*invin + bias)*invout2 -> split-bf16              (agg2)
// MODE 2: v = sum*invin + bias -> fp32                                  (agg3)
template <int F4, int MODE>
__global__ __launch_bounds__(256)
void agg_kernel(const float* __restrict__ H, const int* __restrict__ csr,
                const int* __restrict__ rowstart, const int* __restrict__ degi,
                const float* __restrict__ pre, const float* __restrict__ invin,
                const float* __restrict__ bias, const float* __restrict__ invout2,
                float* __restrict__ outf,
                __nv_bfloat16* __restrict__ outh, __nv_bfloat16* __restrict__ outl,
                int n) {
    int w = (blockIdx.x * blockDim.x + threadIdx.x) >> 5;
    if (w >= n) return;
    int lane = threadIdx.x & 31;
    int start = rowstart[w];
    int deg = degi[w];

    float4 acc = make_float4(0.f, 0.f, 0.f, 0.f);
    const float4* Hv = reinterpret_cast<const float4*>(H);

    for (int base = 0; base < deg; base += 32) {
        int nchunk = min(32, deg - base);
        int idx = 0;
        float pval = 1.0f;
        if (lane < nchunk) {
            idx = csr[start + base + lane];
            if (MODE == 0) pval = pre[idx];
        }
        #pragma unroll 4
        for (int j = 0; j < nchunk; ++j) {
            int s = __shfl_sync(0xffffffffu, idx, j);
            float p = (MODE == 0) ? __shfl_sync(0xffffffffu, pval, j) : 1.0f;
            if (lane < F4) {
                float4 v = Hv[(size_t)s * F4 + lane];
                if (MODE == 0) {
                    acc.x = fmaf(v.x, p, acc.x);
                    acc.y = fmaf(v.y, p, acc.y);
                    acc.z = fmaf(v.z, p, acc.z);
                    acc.w = fmaf(v.w, p, acc.w);
                } else {
                    acc.x += v.x; acc.y += v.y; acc.z += v.z; acc.w += v.w;
                }
            }
        }
    }

    if (lane < F4) {
        if (MODE >= 1) {
            float s = invin[w];
            float4 b = reinterpret_cast<const float4*>(bias)[lane];
            acc.x = acc.x * s + b.x;
            acc.y = acc.y * s + b.y;
            acc.z = acc.z * s + b.z;
            acc.w = acc.w * s + b.w;
        }
        if (MODE == 1) {
            float s2 = invout2[w];
            acc.x = fmaxf(acc.x, 0.f) * s2; acc.y = fmaxf(acc.y, 0.f) * s2;
            acc.z = fmaxf(acc.z, 0.f) * s2; acc.w = fmaxf(acc.w, 0.f) * s2;
        }
        if (MODE == 2) {
            reinterpret_cast<float4*>(outf)[(size_t)w * F4 + lane] = acc;
        } else {
            uint32_t h0, l0, h1, l1;
            split2(acc.x, acc.y, h0, l0);
            split2(acc.z, acc.w, h1, l1);
            size_t base2 = (size_t)w * (F4 * 4) + lane * 4;
            *reinterpret_cast<uint2*>(outh + base2) = make_uint2(h0, h1);
            *reinterpret_cast<uint2*>(outl + base2) = make_uint2(l0, l1);
        }
    }
}

// ---------------- mma.sync split-bf16 GEMM: pre-split A, 128x64 tile ----------------
__device__ __forceinline__ void mma16816(float* d, const uint32_t* a, uint32_t b0, uint32_t b1) {
    asm("mma.sync.aligned.m16n8k16.row.col.f32.bf16.bf16.f32 "
        "{%0,%1,%2,%3}, {%4,%5,%6,%7}, {%8,%9}, {%0,%1,%2,%3};"
        : "+f"(d[0]), "+f"(d[1]), "+f"(d[2]), "+f"(d[3])
        : "r"(a[0]), "r"(a[1]), "r"(a[2]), "r"(a[3]), "r"(b0), "r"(b1));
}

__device__ __forceinline__ void ldmat_x4(uint32_t* r, uint32_t saddr) {
    asm volatile("ldmatrix.sync.aligned.m8n8.x4.shared.b16 {%0,%1,%2,%3}, [%4];"
                 : "=r"(r[0]), "=r"(r[1]), "=r"(r[2]), "=r"(r[3]) : "r"(saddr));
}

__device__ __forceinline__ uint32_t smem_u32(const void* p) {
    uint32_t a;
    asm("{ .reg .u64 t; cvta.to.shared.u64 t, %1; cvt.u32.u64 %0, t; }" : "=r"(a) : "l"(p));
    return a;
}

constexpr int MMA_BK = 32;
constexpr int MMA_LDS = MMA_BK + 8;   // 80B rows -> conflict-free ldmatrix
constexpr int TNT = 64;               // CTA N-tile
constexpr int NI = 4;                 // 8-col groups per warp (warp tile 32x32)

// EPI1: v = relu(acc*invin[r]+bias[c])*invout[r] -> split-bf16 out (Ch/Cl)
// else: plain fp32 out (Cf)
template <bool EPI1>
__global__ __launch_bounds__(256, 3)
void mgemm_kernel(const __nv_bfloat16* __restrict__ Agh,
                  const __nv_bfloat16* __restrict__ Agl,
                  const __nv_bfloat16* __restrict__ Wth,
                  const __nv_bfloat16* __restrict__ Wtl,
                  float* __restrict__ Cf,
                  __nv_bfloat16* __restrict__ Ch, __nv_bfloat16* __restrict__ Cl,
                  int M, int N, int K,
                  const float* __restrict__ invin,
                  const float* __restrict__ bias,
                  const float* __restrict__ invout) {
    __shared__ __align__(16) __nv_bfloat16 Ah[128][MMA_LDS];
    __shared__ __align__(16) __nv_bfloat16 Al[128][MMA_LDS];
    __shared__ __align__(16) __nv_bfloat16 Wh[TNT][MMA_LDS];
    __shared__ __align__(16) __nv_bfloat16 Wl[TNT][MMA_LDS];

    const int tid = threadIdx.x;
    const int lane = tid & 31;
    const int wid = tid >> 5;
    const int m0 = blockIdx.x * 128;
    const int n0 = blockIdx.y * TNT;
    const int wm = (wid & 3) * 32;
    const int wn = (wid >> 2) * 32;
    const int g = lane >> 2;
    const int tg2 = (lane & 3) * 2;

    const int arow = lane & 15;
    const int akoff = (lane >> 4) * 8;
    const int wrow = (lane & 7) + ((lane >> 4) << 3);
    const int wkoff = (lane & 8) ? 8 : 0;

    const uint32_t uAh = smem_u32(&Ah[0][0]);
    const uint32_t uAl = smem_u32(&Al[0][0]);
    const uint32_t uWh = smem_u32(&Wh[0][0]);
    const uint32_t uWl = smem_u32(&Wl[0][0]);

    float acc[2][NI][4] = {};
    const uint4 z4 = make_uint4(0u, 0u, 0u, 0u);

    for (int k0 = 0; k0 < K; k0 += MMA_BK) {
        if (k0 > 0) __syncthreads();
        // --- A chunk: copy pre-split bf16 (uint4) ---
        #pragma unroll
        for (int it = 0; it < 4; ++it) {
            int idx = it * 256 + tid;       // 0..1023
            bool lo = idx >= 512;
            int idx2 = idx & 511;
            int row = idx2 >> 2;            // 0..127
            int seg = idx2 & 3;             // 8-elem segment
            int gr = m0 + row;
            const __nv_bfloat16* gsrc = (lo ? Agl : Agh) + (size_t)gr * K + k0 + seg * 8;
            uint4 v = (gr < M) ? *reinterpret_cast<const uint4*>(gsrc) : z4;
            __nv_bfloat16* sdst = (lo ? &Al[0][0] : &Ah[0][0]) + row * MMA_LDS + seg * 8;
            *reinterpret_cast<uint4*>(sdst) = v;
        }
        // --- W chunk: copy pre-split bf16 (uint4) ---
        #pragma unroll
        for (int it = 0; it < 2; ++it) {
            int idx = it * 256 + tid;       // 0..511
            bool lo = idx >= 256;
            int idx2 = idx & 255;
            int n = idx2 >> 2;              // 0..63
            int seg = idx2 & 3;
            int gn = n0 + n;
            uint4 v = z4;
            if (gn < N)
                v = *reinterpret_cast<const uint4*>((lo ? Wtl : Wth) + (size_t)gn * K + k0 + seg * 8);
            __nv_bfloat16* sdst = (lo ? &Wl[0][0] : &Wh[0][0]) + n * MMA_LDS + seg * 8;
            *reinterpret_cast<uint4*>(sdst) = v;
        }
        __syncthreads();

        // --- compute: ldmatrix once, 3 split passes fused ---
        #pragma unroll
        for (int ks = 0; ks < 2; ++ks) {
            int kk = ks * 16;
            uint32_t ah[2][4], al[2][4];
            #pragma unroll
            for (int mi = 0; mi < 2; ++mi) {
                uint32_t aoff = (uint32_t)(((wm + mi * 16 + arow) * MMA_LDS + kk + akoff) * 2);
                ldmat_x4(ah[mi], uAh + aoff);
                ldmat_x4(al[mi], uAl + aoff);
            }
            #pragma unroll
            for (int nj = 0; nj < NI / 2; ++nj) {
                uint32_t wh[4], wl[4];
                uint32_t woff = (uint32_t)(((wn + nj * 16 + wrow) * MMA_LDS + kk + wkoff) * 2);
                ldmat_x4(wh, uWh + woff);
                ldmat_x4(wl, uWl + woff);
                #pragma unroll
                for (int q = 0; q < 2; ++q) {
                    int ni = nj * 2 + q;
                    uint32_t b0h = wh[q * 2], b1h = wh[q * 2 + 1];
                    uint32_t b0l = wl[q * 2], b1l = wl[q * 2 + 1];
                    mma16816(acc[0][ni], ah[0], b0h, b1h);
                    mma16816(acc[1][ni], ah[1], b0h, b1h);
                    mma16816(acc[0][ni], ah[0], b0l, b1l);
                    mma16816(acc[1][ni], ah[1], b0l, b1l);
                    mma16816(acc[0][ni], al[0], b0h, b1h);
                    mma16816(acc[1][ni], al[1], b0h, b1h);
                }
            }
        }
    }

    // ---- epilogue ----
    #pragma unroll
    for (int mi = 0; mi < 2; ++mi) {
        int r0 = m0 + wm + mi * 16 + g;
        int r1 = r0 + 8;
        float i0 = 1.f, i1 = 1.f, o0 = 1.f, o1 = 1.f;
        if (EPI1) {
            if (r0 < M) { i0 = invin[r0]; o0 = invout[r0]; }
            if (r1 < M) { i1 = invin[r1]; o1 = invout[r1]; }
        }
        #pragma unroll
        for (int ni = 0; ni < NI; ++ni) {
            int col = n0 + wn + ni * 8 + tg2;
            if (col >= N) continue;
            if (EPI1) {
                float bx = bias[col], by = bias[col + 1];
                if (r0 < M) {
                    float vx = fmaxf(acc[mi][ni][0] * i0 + bx, 0.f) * o0;
                    float vy = fmaxf(acc[mi][ni][1] * i0 + by, 0.f) * o0;
                    uint32_t h, l;
                    split2(vx, vy, h, l);
                    *reinterpret_cast<uint32_t*>(Ch + (size_t)r0 * N + col) = h;
                    *reinterpret_cast<uint32_t*>(Cl + (size_t)r0 * N + col) = l;
                }
                if (r1 < M) {
                    float vx = fmaxf(acc[mi][ni][2] * i1 + bx, 0.f) * o1;
                    float vy = fmaxf(acc[mi][ni][3] * i1 + by, 0.f) * o1;
                    uint32_t h, l;
                    split2(vx, vy, h, l);
                    *reinterpret_cast<uint32_t*>(Ch + (size_t)r1 * N + col) = h;
                    *reinterpret_cast<uint32_t*>(Cl + (size_t)r1 * N + col) = l;
                }
            } else {
                if (r0 < M)
                    *reinterpret_cast<float2*>(Cf + (size_t)r0 * N + col) =
                        make_float2(acc[mi][ni][0], acc[mi][ni][1]);
                if (r1 < M)
                    *reinterpret_cast<float2*>(Cf + (size_t)r1 * N + col) =
                        make_float2(acc[mi][ni][2], acc[mi][ni][3]);
            }
        }
    }
}

// ---------------- launch ----------------
static inline int cdiv(int a, int b) { return (a + b - 1) / b; }

extern "C" void kernel_launch(void* const* d_in, const int* in_sizes, int n_in,
                              void* d_out, int out_size) {
    const float* feat = (const float*)d_in[0];
    const int*   src  = (const int*)d_in[1];
    const int*   dst  = (const int*)d_in[2];
    const float* W1   = (const float*)d_in[3];
    const float* b1   = (const float*)d_in[4];
    const float* W2   = (const float*)d_in[5];
    const float* b2   = (const float*)d_in[6];
    const float* W3   = (const float*)d_in[7];
    const float* b3   = (const float*)d_in[8];
    const int E = in_sizes[1];
    float* out = (float*)d_out;

    float *T2, *T3, *invout, *invin;
    int *idegi, *rowstart, *csr;
    __nv_bfloat16 *a1h, *a1l, *x1h, *x1l, *x2h, *x2l;
    __nv_bfloat16 *wt1h, *wt1l, *wt2h, *wt2l, *wt3h, *wt3l;
    cudaGetSymbolAddress((void**)&a1h, g_A1h);
    cudaGetSymbolAddress((void**)&a1l, g_A1l);
    cudaGetSymbolAddress((void**)&x1h, g_X1h);
    cudaGetSymbolAddress((void**)&x1l, g_X1l);
    cudaGetSymbolAddress((void**)&x2h, g_X2h);
    cudaGetSymbolAddress((void**)&x2l, g_X2l);
    cudaGetSymbolAddress((void**)&T2, g_T2);
    cudaGetSymbolAddress((void**)&T3, g_T3);
    cudaGetSymbolAddress((void**)&invout, g_invout);
    cudaGetSymbolAddress((void**)&invin, g_invin);
    cudaGetSymbolAddress((void**)&idegi, g_idegi);
    cudaGetSymbolAddress((void**)&rowstart, g_rowstart);
    cudaGetSymbolAddress((void**)&csr, g_csr);
    cudaGetSymbolAddress((void**)&wt1h, g_Wt1h);
    cudaGetSymbolAddress((void**)&wt1l, g_Wt1l);
    cudaGetSymbolAddress((void**)&wt2h, g_Wt2h);
    cudaGetSymbolAddress((void**)&wt2l, g_Wt2l);
    cudaGetSymbolAddress((void**)&wt3h, g_Wt3h);
    cudaGetSymbolAddress((void**)&wt3l, g_Wt3l);

    const int T = 256;
    const int MG = cdiv(NN, 128);
    const int AGG_GRID = cdiv(NN, 8);

    // fused build
    build_kernel<<<NBLD, TBLD>>>(src, dst, E, W1, W2, W3);

    // ---- Layer 1 ----
    // agg1: gather feat (pre=invout), write split-bf16 A1
    agg_kernel<32, 0><<<AGG_GRID, T>>>(feat, csr, rowstart, idegi, invout,
                                       nullptr, nullptr, nullptr,
                                       nullptr, a1h, a1l, NN);
    // GEMM1: X1 = relu(A1@W1 * invin + b1) * invout -> split-bf16
    {
        dim3 grid(MG, cdiv(256, TNT));
        mgemm_kernel<true><<<grid, T>>>(a1h, a1l, wt1h, wt1l,
                                        nullptr, x1h, x1l,
                                        NN, 256, 128, invin, b1, invout);
    }

    // ---- Layer 2 ----
    // GEMM2: T2 = X1 @ W2 (fp32 out)
    {
        dim3 grid(MG, cdiv(128, TNT));
        mgemm_kernel<false><<<grid, T>>>(x1h, x1l, wt2h, wt2l,
                                         T2, nullptr, nullptr,
                                         NN, 128, 256, nullptr, nullptr, nullptr);
    }
    // agg2: gather T2, relu(*invin+b2)*invout -> split-bf16 X2
    agg_kernel<32, 1><<<AGG_GRID, T>>>(T2, csr, rowstart, idegi, nullptr,
                                       invin, b2, invout,
                                       nullptr, x2h, x2l, NN);

    // ---- Layer 3 ----
    // GEMM3: T3 = X2 @ W3 (fp32 out)
    {
        dim3 grid(MG, cdiv(40, TNT));
        mgemm_kernel<false><<<grid, T>>>(x2h, x2l, wt3h, wt3l,
                                         T3, nullptr, nullptr,
                                         NN, 40, 128, nullptr, nullptr, nullptr);
    }
    // agg3: gather T3, *invin + b3 -> fp32 out
    agg_kernel<10, 2><<<AGG_GRID, T>>>(T3, csr, rowstart, idegi, nullptr,
                                       invin, b3, nullptr,
                                       out, nullptr, nullptr, NN);
}